// round 11
// baseline (speedup 1.0000x reference)
#include <cuda_runtime.h>
#include <cstddef>
#include <cstdint>

#define N_NODES 100000
#define N_EDGES 1600000
#define IN_F    48
#define EDGE_F  32
#define CAT_F   96
#define HID_F   128
#define OUT_F   64

#define SCAN_T  1024
#define CHUNK   ((N_NODES + SCAN_T - 1) / SCAN_T)

__device__ int   g_deg_i [N_NODES];
__device__ int   g_rowptr[N_NODES + 1];
__device__ int   g_cursor[N_NODES];
__device__ int   g_csr_eid[N_EDGES];
__device__ int   g_csr_src[N_EDGES];
__device__ float g_msg [(size_t)N_EDGES * IN_F];
__device__ float g_h   [(size_t)N_NODES * CAT_F];
__device__ float g_hn1 [(size_t)N_NODES * CAT_F];
__device__ float g_h1  [(size_t)N_NODES * HID_F];
__device__ float g_z2  [(size_t)N_NODES * OUT_F];

// ---------------- CSR build ----------------
__global__ void k_zero_hist() {
    int i = blockIdx.x * blockDim.x + threadIdx.x;
    if (i < N_NODES) g_deg_i[i] = 0;
}

__global__ void __launch_bounds__(256) k_hist(const int* __restrict__ dst) {
    int e = blockIdx.x * blockDim.x + threadIdx.x;
    if (e < N_EDGES) atomicAdd(&g_deg_i[dst[e]], 1);
}

__global__ void __launch_bounds__(SCAN_T) k_scan() {
    __shared__ int sh[SCAN_T];
    int t = threadIdx.x;
    int start = t * CHUNK;
    int end = start + CHUNK; if (end > N_NODES) end = N_NODES;
    int s = 0;
    if (start < N_NODES) for (int i = start; i < end; i++) s += g_deg_i[i];
    sh[t] = s;
    __syncthreads();
    for (int d = 1; d < SCAN_T; d <<= 1) {
        int v = (t >= d) ? sh[t - d] : 0;
        __syncthreads();
        sh[t] += v;
        __syncthreads();
    }
    int off = sh[t] - s;
    if (start < N_NODES) {
        for (int i = start; i < end; i++) {
            g_rowptr[i] = off;
            g_cursor[i] = off;
            off += g_deg_i[i];
        }
        if (end == N_NODES) g_rowptr[N_NODES] = off;
    }
}

__global__ void __launch_bounds__(256) k_place(const int* __restrict__ src,
                                               const int* __restrict__ dst) {
    int e = blockIdx.x * blockDim.x + threadIdx.x;
    if (e >= N_EDGES) return;
    int p = atomicAdd(&g_cursor[dst[e]], 1);
    g_csr_eid[p] = e;
    g_csr_src[p] = src[e];
}

// ---------------- edge MLP: warp per 8 CSR slots (sage1-style blocking) ----------------
// msg[p] = relu(efeat[eid] @ We + be) * nfeat[src];  lane owns 2 output features.
#define EMLP_TILES (N_EDGES / 8)     // 200000
__global__ void __launch_bounds__(256) k_edge_mlp2(const float* __restrict__ efeat,
                                                   const float* __restrict__ nfeat,
                                                   const float* __restrict__ We,
                                                   const float* __restrict__ be) {
    __shared__ __align__(16) float sWe[EDGE_F * IN_F + 16];   // padded (inactive-lane reads)
    __shared__ float sbe[IN_F];
    for (int i = threadIdx.x; i < EDGE_F * IN_F; i += 256) sWe[i] = We[i];
    for (int i = threadIdx.x; i < IN_F; i += 256) sbe[i] = be[i];
    __syncthreads();

    int warp = threadIdx.x >> 5;
    int lane = threadIdx.x & 31;
    int c = lane * 2;
    bool active = c < IN_F;           // lanes 0..23

    for (int t = blockIdx.x * 8 + warp; t < EMLP_TILES; t += gridDim.x * 8) {
        int p0 = t * 8;
        int eid0 = 0, src0 = 0;
        if (lane < 8) { eid0 = g_csr_eid[p0 + lane]; src0 = g_csr_src[p0 + lane]; }
        int eids[8], srcs[8];
        #pragma unroll
        for (int j = 0; j < 8; j++) {
            eids[j] = __shfl_sync(0xffffffffu, eid0, j);
            srcs[j] = __shfl_sync(0xffffffffu, src0, j);
        }

        float acc[8][2];
        #pragma unroll
        for (int j = 0; j < 8; j++) { acc[j][0] = 0.f; acc[j][1] = 0.f; }

        #pragma unroll 1
        for (int k0 = 0; k0 < EDGE_F; k0 += 4) {
            float4 xv[8];
            #pragma unroll
            for (int j = 0; j < 8; j++)
                xv[j] = *(const float4*)(efeat + (size_t)eids[j] * EDGE_F + k0);
            #pragma unroll
            for (int kk = 0; kk < 4; kk++) {
                float2 w = *(const float2*)&sWe[(k0 + kk) * IN_F + c];
                #pragma unroll
                for (int j = 0; j < 8; j++) {
                    float x = (kk == 0) ? xv[j].x : (kk == 1) ? xv[j].y : (kk == 2) ? xv[j].z : xv[j].w;
                    acc[j][0] = fmaf(x, w.x, acc[j][0]);
                    acc[j][1] = fmaf(x, w.y, acc[j][1]);
                }
            }
        }

        if (active) {
            float b0 = sbe[c], b1 = sbe[c + 1];
            #pragma unroll
            for (int j = 0; j < 8; j++) {
                float2 nf = *(const float2*)(nfeat + (size_t)srcs[j] * IN_F + c);
                float2 m;
                m.x = fmaxf(acc[j][0] + b0, 0.f) * nf.x;
                m.y = fmaxf(acc[j][1] + b1, 0.f) * nf.y;
                *(float2*)(g_msg + (size_t)(p0 + j) * IN_F + c) = m;
            }
        }
    }
}

// ---------------- gather0: h = [nfeat | mean(msg)] ----------------
__global__ void __launch_bounds__(256) k_gather0(const float* __restrict__ nfeat) {
    int gw   = (blockIdx.x * 256 + threadIdx.x) >> 5;
    int lane = threadIdx.x & 31;
    int half = lane >> 4, sub = lane & 15;
    int node = gw * 2 + half;
    if (node >= N_NODES) return;
    bool active = sub < (IN_F / 4);

    int lo = g_rowptr[node], hi = g_rowptr[node + 1];
    float4 a0 = make_float4(0.f,0.f,0.f,0.f), a1 = make_float4(0.f,0.f,0.f,0.f);
    if (active) {
        int p = lo;
        for (; p + 1 < hi; p += 2) {
            float4 v0 = *(const float4*)(g_msg + (size_t)p       * IN_F + sub * 4);
            float4 v1 = *(const float4*)(g_msg + (size_t)(p + 1) * IN_F + sub * 4);
            a0.x += v0.x; a0.y += v0.y; a0.z += v0.z; a0.w += v0.w;
            a1.x += v1.x; a1.y += v1.y; a1.z += v1.z; a1.w += v1.w;
        }
        if (p < hi) {
            float4 v = *(const float4*)(g_msg + (size_t)p * IN_F + sub * 4);
            a0.x += v.x; a0.y += v.y; a0.z += v.z; a0.w += v.w;
        }
    }
    if (active) {
        float invd = 1.0f / fmaxf((float)(hi - lo), 1.0f);
        float4 nf = *(const float4*)(nfeat + (size_t)node * IN_F + sub * 4);
        *(float4*)(g_h + (size_t)node * CAT_F + sub * 4) = nf;
        float4 acc;
        acc.x = (a0.x + a1.x) * invd; acc.y = (a0.y + a1.y) * invd;
        acc.z = (a0.z + a1.z) * invd; acc.w = (a0.w + a1.w) * invd;
        *(float4*)(g_h + (size_t)node * CAT_F + IN_F + sub * 4) = acc;
    }
}

// ---------------- gather1: hn1 = mean(h[src]) ----------------
__global__ void __launch_bounds__(256) k_gather_h() {
    int node = (blockIdx.x * 256 + threadIdx.x) >> 5;
    int lane = threadIdx.x & 31;
    if (node >= N_NODES) return;
    bool active = lane < (CAT_F / 4);

    int lo = g_rowptr[node], hi = g_rowptr[node + 1];
    float4 a0 = make_float4(0.f,0.f,0.f,0.f), a1 = make_float4(0.f,0.f,0.f,0.f);
    int p = lo;
    for (; p + 1 < hi; p += 2) {
        int s0 = g_csr_src[p], s1 = g_csr_src[p + 1];
        if (active) {
            float4 v0 = *(const float4*)(g_h + (size_t)s0 * CAT_F + lane * 4);
            float4 v1 = *(const float4*)(g_h + (size_t)s1 * CAT_F + lane * 4);
            a0.x += v0.x; a0.y += v0.y; a0.z += v0.z; a0.w += v0.w;
            a1.x += v1.x; a1.y += v1.y; a1.z += v1.z; a1.w += v1.w;
        }
    }
    if (p < hi) {
        int s = g_csr_src[p];
        if (active) {
            float4 v = *(const float4*)(g_h + (size_t)s * CAT_F + lane * 4);
            a0.x += v.x; a0.y += v.y; a0.z += v.z; a0.w += v.w;
        }
    }
    if (active) {
        float invd = 1.0f / fmaxf((float)(hi - lo), 1.0f);
        float4 acc;
        acc.x = (a0.x + a1.x) * invd; acc.y = (a0.y + a1.y) * invd;
        acc.z = (a0.z + a1.z) * invd; acc.w = (a0.w + a1.w) * invd;
        *(float4*)(g_hn1 + (size_t)node * CAT_F + lane * 4) = acc;
    }
}

// ---------------- SAGEConv1 (smem-W, grid-stride) ----------------
#define S1_SMEM ((192 * 128 + 128) * 4)
#define N_TILES64 ((N_NODES + 63) / 64)

__global__ void __launch_bounds__(256) k_sage1_s(const float* __restrict__ W1s,
                                                 const float* __restrict__ W1n,
                                                 const float* __restrict__ b1) {
    extern __shared__ float sW[];
    float* sB = sW + 192 * 128;
    for (int i = threadIdx.x; i < 96 * 128 / 4; i += 256) {
        ((float4*)sW)[i]                 = ((const float4*)W1s)[i];
        ((float4*)sW)[96 * 128 / 4 + i]  = ((const float4*)W1n)[i];
    }
    for (int i = threadIdx.x; i < 128; i += 256) sB[i] = b1[i];
    __syncthreads();

    int warp = threadIdx.x >> 5;
    int lane = threadIdx.x & 31;
    int c = lane * 4;

    for (int tile = blockIdx.x; tile < N_TILES64; tile += gridDim.x) {
        int n0 = tile * 64 + warp * 8;
        if (n0 >= N_NODES) continue;

        float acc[8][4];
        #pragma unroll
        for (int j = 0; j < 8; j++) { acc[j][0]=0.f; acc[j][1]=0.f; acc[j][2]=0.f; acc[j][3]=0.f; }

        #pragma unroll 1
        for (int hf = 0; hf < 2; hf++) {
            const float* xb = (hf == 0 ? g_h : g_hn1) + (size_t)n0 * CAT_F;
            const float* Ws = sW + hf * 96 * 128;
            #pragma unroll 1
            for (int k0 = 0; k0 < CAT_F; k0 += 4) {
                float4 xv[8];
                #pragma unroll
                for (int j = 0; j < 8; j++) xv[j] = *(const float4*)(xb + (size_t)j * CAT_F + k0);
                #pragma unroll
                for (int kk = 0; kk < 4; kk++) {
                    float4 w = *(const float4*)&Ws[(k0 + kk) * 128 + c];
                    #pragma unroll
                    for (int j = 0; j < 8; j++) {
                        float x = (kk == 0) ? xv[j].x : (kk == 1) ? xv[j].y : (kk == 2) ? xv[j].z : xv[j].w;
                        acc[j][0] = fmaf(x, w.x, acc[j][0]);
                        acc[j][1] = fmaf(x, w.y, acc[j][1]);
                        acc[j][2] = fmaf(x, w.z, acc[j][2]);
                        acc[j][3] = fmaf(x, w.w, acc[j][3]);
                    }
                }
            }
        }

        float4 b = *(const float4*)&sB[c];
        #pragma unroll
        for (int j = 0; j < 8; j++) {
            float4 r;
            r.x = fmaxf(acc[j][0] + b.x, 0.f);
            r.y = fmaxf(acc[j][1] + b.y, 0.f);
            r.z = fmaxf(acc[j][2] + b.z, 0.f);
            r.w = fmaxf(acc[j][3] + b.w, 0.f);
            *(float4*)(g_h1 + (size_t)(n0 + j) * HID_F + c) = r;
        }
    }
}

// ---------------- premul2 (smem-W, grid-stride): z2 = h1 @ W2n ----------------
__global__ void __launch_bounds__(256) k_premul2_s(const float* __restrict__ W2n) {
    __shared__ __align__(16) float sW[128 * 64];
    for (int i = threadIdx.x; i < 128 * 64 / 4; i += 256)
        ((float4*)sW)[i] = ((const float4*)W2n)[i];
    __syncthreads();

    int warp = threadIdx.x >> 5;
    int lane = threadIdx.x & 31;
    int c = lane * 2;

    for (int tile = blockIdx.x; tile < N_TILES64; tile += gridDim.x) {
        int n0 = tile * 64 + warp * 8;
        if (n0 >= N_NODES) continue;

        float acc[8][2];
        #pragma unroll
        for (int j = 0; j < 8; j++) { acc[j][0]=0.f; acc[j][1]=0.f; }

        const float* xb = g_h1 + (size_t)n0 * HID_F;
        #pragma unroll 1
        for (int k0 = 0; k0 < HID_F; k0 += 4) {
            float4 xv[8];
            #pragma unroll
            for (int j = 0; j < 8; j++) xv[j] = *(const float4*)(xb + (size_t)j * HID_F + k0);
            #pragma unroll
            for (int kk = 0; kk < 4; kk++) {
                float2 w = *(const float2*)&sW[(k0 + kk) * 64 + c];
                #pragma unroll
                for (int j = 0; j < 8; j++) {
                    float x = (kk == 0) ? xv[j].x : (kk == 1) ? xv[j].y : (kk == 2) ? xv[j].z : xv[j].w;
                    acc[j][0] = fmaf(x, w.x, acc[j][0]);
                    acc[j][1] = fmaf(x, w.y, acc[j][1]);
                }
            }
        }

        #pragma unroll
        for (int j = 0; j < 8; j++) {
            float2 r; r.x = acc[j][0]; r.y = acc[j][1];
            *(float2*)(g_z2 + (size_t)(n0 + j) * OUT_F + c) = r;
        }
    }
}

// ---------------- sage2 fused (smem-W, grid-stride) ----------------
__global__ void __launch_bounds__(256) k_sage2f_s(const float* __restrict__ W2s,
                                                  const float* __restrict__ b2,
                                                  float* __restrict__ out) {
    __shared__ __align__(16) float sW[128 * 64];
    __shared__ float sB[64];
    for (int i = threadIdx.x; i < 128 * 64 / 4; i += 256)
        ((float4*)sW)[i] = ((const float4*)W2s)[i];
    for (int i = threadIdx.x; i < 64; i += 256) sB[i] = b2[i];
    __syncthreads();

    int warp = threadIdx.x >> 5;
    int lane = threadIdx.x & 31;
    int c = lane * 2;

    for (int tile = blockIdx.x; tile < N_TILES64; tile += gridDim.x) {
        int n0 = tile * 64 + warp * 8;
        if (n0 >= N_NODES) continue;

        float acc[8][2];
        #pragma unroll
        for (int j = 0; j < 8; j++) { acc[j][0]=0.f; acc[j][1]=0.f; }

        const float* xb = g_h1 + (size_t)n0 * HID_F;
        #pragma unroll 1
        for (int k0 = 0; k0 < HID_F; k0 += 4) {
            float4 xv[8];
            #pragma unroll
            for (int j = 0; j < 8; j++) xv[j] = *(const float4*)(xb + (size_t)j * HID_F + k0);
            #pragma unroll
            for (int kk = 0; kk < 4; kk++) {
                float2 w = *(const float2*)&sW[(k0 + kk) * 64 + c];
                #pragma unroll
                for (int j = 0; j < 8; j++) {
                    float x = (kk == 0) ? xv[j].x : (kk == 1) ? xv[j].y : (kk == 2) ? xv[j].z : xv[j].w;
                    acc[j][0] = fmaf(x, w.x, acc[j][0]);
                    acc[j][1] = fmaf(x, w.y, acc[j][1]);
                }
            }
        }

        #pragma unroll 1
        for (int j = 0; j < 8; j++) {
            int node = n0 + j;
            int lo = g_rowptr[node], hi = g_rowptr[node + 1];
            float2 a0 = make_float2(0.f, 0.f), a1 = make_float2(0.f, 0.f);
            int p = lo;
            for (; p + 1 < hi; p += 2) {
                int s0 = g_csr_src[p], s1 = g_csr_src[p + 1];
                float2 v0 = *(const float2*)(g_z2 + (size_t)s0 * OUT_F + c);
                float2 v1 = *(const float2*)(g_z2 + (size_t)s1 * OUT_F + c);
                a0.x += v0.x; a0.y += v0.y;
                a1.x += v1.x; a1.y += v1.y;
            }
            if (p < hi) {
                int s = g_csr_src[p];
                float2 v = *(const float2*)(g_z2 + (size_t)s * OUT_F + c);
                a0.x += v.x; a0.y += v.y;
            }
            float invd = 1.0f / fmaxf((float)(hi - lo), 1.0f);
            acc[j][0] += (a0.x + a1.x) * invd;
            acc[j][1] += (a0.y + a1.y) * invd;
        }

        float2 b = *(const float2*)&sB[c];
        #pragma unroll
        for (int j = 0; j < 8; j++) {
            float2 r;
            r.x = acc[j][0] + b.x;
            r.y = acc[j][1] + b.y;
            *(float2*)(out + (size_t)(n0 + j) * OUT_F + c) = r;
        }
    }
}

extern "C" void kernel_launch(void* const* d_in, const int* in_sizes, int n_in,
                              void* d_out, int out_size) {
    const float* nfeat = (const float*)d_in[0];
    const float* efeat = (const float*)d_in[1];
    const int*   src   = (const int*)  d_in[2];
    const int*   dst   = (const int*)  d_in[3];
    const float* We    = (const float*)d_in[4];
    const float* be    = (const float*)d_in[5];
    const float* W1s   = (const float*)d_in[6];
    const float* W1n   = (const float*)d_in[7];
    const float* b1    = (const float*)d_in[8];
    const float* W2s   = (const float*)d_in[9];
    const float* W2n   = (const float*)d_in[10];
    const float* b2    = (const float*)d_in[11];
    float* out = (float*)d_out;

    const int TPB = 256;
    const int edge_blocks = (N_EDGES + TPB - 1) / TPB;
    const int node_blocks = (N_NODES + TPB - 1) / TPB;
    const int g0_blocks   = (N_NODES + 15) / 16;
    const int gw_blocks   = (N_NODES + 7) / 8;
    const int s1_blocks   = 296;
    const int s2_blocks   = 592;
    const int emlp_blocks = 1184;   // persistent grid-stride (8 SM waves)

    cudaFuncSetAttribute(k_sage1_s, cudaFuncAttributeMaxDynamicSharedMemorySize, S1_SMEM);

    k_zero_hist<<<node_blocks, TPB>>>();
    k_hist     <<<edge_blocks, TPB>>>(dst);
    k_scan     <<<1, SCAN_T>>>();
    k_place    <<<edge_blocks, TPB>>>(src, dst);
    k_edge_mlp2<<<emlp_blocks, TPB>>>(efeat, nfeat, We, be);
    k_gather0  <<<g0_blocks, TPB>>>(nfeat);
    k_gather_h <<<gw_blocks, TPB>>>();
    k_sage1_s  <<<s1_blocks, TPB, S1_SMEM>>>(W1s, W1n, b1);
    k_premul2_s<<<s2_blocks, TPB>>>(W2n);
    k_sage2f_s <<<s2_blocks, TPB>>>(W2s, b2, out);
}

// round 13
// speedup vs baseline: 1.1906x; 1.1906x over previous
#include <cuda_runtime.h>
#include <cstddef>
#include <cstdint>

#define N_NODES 100000
#define N_EDGES 1600000
#define IN_F    48
#define EDGE_F  32
#define CAT_F   96
#define HID_F   128
#define OUT_F   64

#define SCAN_T  1024
#define CHUNK   ((N_NODES + SCAN_T - 1) / SCAN_T)

__device__ int   g_deg_i [N_NODES];
__device__ int   g_rowptr[N_NODES + 1];
__device__ int   g_cursor[N_NODES];
__device__ int   g_csr_eid[N_EDGES];
__device__ int   g_csr_src[N_EDGES];
__device__ float g_msg [(size_t)N_EDGES * IN_F];
__device__ float g_h   [(size_t)N_NODES * CAT_F];
__device__ float g_hn1 [(size_t)N_NODES * CAT_F];
__device__ float g_h1  [(size_t)N_NODES * HID_F];
__device__ float g_z   [(size_t)N_NODES * 128];   // [self(64) | neigh(64)] pre-agg

// ---------------- CSR build ----------------
__global__ void k_zero_hist() {
    int i = blockIdx.x * blockDim.x + threadIdx.x;
    if (i < N_NODES) g_deg_i[i] = 0;
}

__global__ void __launch_bounds__(256) k_hist(const int* __restrict__ dst) {
    int e = blockIdx.x * blockDim.x + threadIdx.x;
    if (e < N_EDGES) atomicAdd(&g_deg_i[dst[e]], 1);
}

__global__ void __launch_bounds__(SCAN_T) k_scan() {
    __shared__ int sh[SCAN_T];
    int t = threadIdx.x;
    int start = t * CHUNK;
    int end = start + CHUNK; if (end > N_NODES) end = N_NODES;
    int s = 0;
    if (start < N_NODES) for (int i = start; i < end; i++) s += g_deg_i[i];
    sh[t] = s;
    __syncthreads();
    for (int d = 1; d < SCAN_T; d <<= 1) {
        int v = (t >= d) ? sh[t - d] : 0;
        __syncthreads();
        sh[t] += v;
        __syncthreads();
    }
    int off = sh[t] - s;
    if (start < N_NODES) {
        for (int i = start; i < end; i++) {
            g_rowptr[i] = off;
            g_cursor[i] = off;
            off += g_deg_i[i];
        }
        if (end == N_NODES) g_rowptr[N_NODES] = off;
    }
}

__global__ void __launch_bounds__(256) k_place(const int* __restrict__ src,
                                               const int* __restrict__ dst) {
    int e = blockIdx.x * blockDim.x + threadIdx.x;
    if (e >= N_EDGES) return;
    int p = atomicAdd(&g_cursor[dst[e]], 1);
    g_csr_eid[p] = e;
    g_csr_src[p] = src[e];
}

// ---------------- edge MLP in CSR order (thread-per-edge) ----------------
__global__ void __launch_bounds__(256) k_edge_mlp(const float* __restrict__ efeat,
                                                  const float* __restrict__ nfeat,
                                                  const float* __restrict__ We,
                                                  const float* __restrict__ be) {
    __shared__ __align__(16) float sWe[EDGE_F * IN_F];
    __shared__ float sbe[IN_F];
    for (int i = threadIdx.x; i < EDGE_F * IN_F; i += blockDim.x) sWe[i] = We[i];
    for (int i = threadIdx.x; i < IN_F; i += blockDim.x) sbe[i] = be[i];
    __syncthreads();

    int p = blockIdx.x * blockDim.x + threadIdx.x;
    if (p >= N_EDGES) return;
    int eid = g_csr_eid[p];
    int s   = g_csr_src[p];

    float ef[EDGE_F];
    const float4* ep = (const float4*)(efeat + (size_t)eid * EDGE_F);
    #pragma unroll
    for (int i = 0; i < EDGE_F / 4; i++) {
        float4 v = ep[i];
        ef[4*i+0] = v.x; ef[4*i+1] = v.y; ef[4*i+2] = v.z; ef[4*i+3] = v.w;
    }

    const float4* np = (const float4*)(nfeat + (size_t)s * IN_F);
    float4*       op = (float4*)(g_msg + (size_t)p * IN_F);

    #pragma unroll 1
    for (int j = 0; j < IN_F / 4; j++) {
        float4 a;
        a.x = sbe[4*j+0]; a.y = sbe[4*j+1]; a.z = sbe[4*j+2]; a.w = sbe[4*j+3];
        #pragma unroll
        for (int k = 0; k < EDGE_F; k++) {
            float4 w = *(const float4*)&sWe[k * IN_F + 4*j];
            a.x = fmaf(ef[k], w.x, a.x);
            a.y = fmaf(ef[k], w.y, a.y);
            a.z = fmaf(ef[k], w.z, a.z);
            a.w = fmaf(ef[k], w.w, a.w);
        }
        a.x = fmaxf(a.x, 0.f); a.y = fmaxf(a.y, 0.f);
        a.z = fmaxf(a.z, 0.f); a.w = fmaxf(a.w, 0.f);
        float4 nf = np[j];
        a.x *= nf.x; a.y *= nf.y; a.z *= nf.z; a.w *= nf.w;
        op[j] = a;
    }
}

// ---------------- gather0: h = [nfeat | mean(msg)] ----------------
__global__ void __launch_bounds__(256) k_gather0(const float* __restrict__ nfeat) {
    int gw   = (blockIdx.x * 256 + threadIdx.x) >> 5;
    int lane = threadIdx.x & 31;
    int half = lane >> 4, sub = lane & 15;
    int node = gw * 2 + half;
    if (node >= N_NODES) return;
    bool active = sub < (IN_F / 4);

    int lo = g_rowptr[node], hi = g_rowptr[node + 1];
    float4 a0 = make_float4(0.f,0.f,0.f,0.f), a1 = make_float4(0.f,0.f,0.f,0.f);
    if (active) {
        int p = lo;
        for (; p + 1 < hi; p += 2) {
            float4 v0 = *(const float4*)(g_msg + (size_t)p       * IN_F + sub * 4);
            float4 v1 = *(const float4*)(g_msg + (size_t)(p + 1) * IN_F + sub * 4);
            a0.x += v0.x; a0.y += v0.y; a0.z += v0.z; a0.w += v0.w;
            a1.x += v1.x; a1.y += v1.y; a1.z += v1.z; a1.w += v1.w;
        }
        if (p < hi) {
            float4 v = *(const float4*)(g_msg + (size_t)p * IN_F + sub * 4);
            a0.x += v.x; a0.y += v.y; a0.z += v.z; a0.w += v.w;
        }
    }
    if (active) {
        float invd = 1.0f / fmaxf((float)(hi - lo), 1.0f);
        float4 nf = *(const float4*)(nfeat + (size_t)node * IN_F + sub * 4);
        *(float4*)(g_h + (size_t)node * CAT_F + sub * 4) = nf;
        float4 acc;
        acc.x = (a0.x + a1.x) * invd; acc.y = (a0.y + a1.y) * invd;
        acc.z = (a0.z + a1.z) * invd; acc.w = (a0.w + a1.w) * invd;
        *(float4*)(g_h + (size_t)node * CAT_F + IN_F + sub * 4) = acc;
    }
}

// ---------------- gather1: hn1 = mean(h[src]) ----------------
__global__ void __launch_bounds__(256) k_gather_h() {
    int node = (blockIdx.x * 256 + threadIdx.x) >> 5;
    int lane = threadIdx.x & 31;
    if (node >= N_NODES) return;
    bool active = lane < (CAT_F / 4);

    int lo = g_rowptr[node], hi = g_rowptr[node + 1];
    float4 a0 = make_float4(0.f,0.f,0.f,0.f), a1 = make_float4(0.f,0.f,0.f,0.f);
    int p = lo;
    for (; p + 1 < hi; p += 2) {
        int s0 = g_csr_src[p], s1 = g_csr_src[p + 1];
        if (active) {
            float4 v0 = *(const float4*)(g_h + (size_t)s0 * CAT_F + lane * 4);
            float4 v1 = *(const float4*)(g_h + (size_t)s1 * CAT_F + lane * 4);
            a0.x += v0.x; a0.y += v0.y; a0.z += v0.z; a0.w += v0.w;
            a1.x += v1.x; a1.y += v1.y; a1.z += v1.z; a1.w += v1.w;
        }
    }
    if (p < hi) {
        int s = g_csr_src[p];
        if (active) {
            float4 v = *(const float4*)(g_h + (size_t)s * CAT_F + lane * 4);
            a0.x += v.x; a0.y += v.y; a0.z += v.z; a0.w += v.w;
        }
    }
    if (active) {
        float invd = 1.0f / fmaxf((float)(hi - lo), 1.0f);
        float4 acc;
        acc.x = (a0.x + a1.x) * invd; acc.y = (a0.y + a1.y) * invd;
        acc.z = (a0.z + a1.z) * invd; acc.w = (a0.w + a1.w) * invd;
        *(float4*)(g_hn1 + (size_t)node * CAT_F + lane * 4) = acc;
    }
}

// ================= persistent tf32 3x-split mma GEMMs =================
#define BSTR 136

static __device__ __forceinline__ uint32_t f2tf32(float x) {
    uint32_t r;
    asm("cvt.rna.tf32.f32 %0, %1;" : "=r"(r) : "f"(x));
    return r;
}
static __device__ __forceinline__ void split2(float x, float& hi, float& lo) {
    hi = __uint_as_float(f2tf32(x));
    lo = __uint_as_float(f2tf32(x - hi));
}
static __device__ __forceinline__ void mma8(float* d, const uint32_t* a, uint32_t b0, uint32_t b1) {
    asm volatile(
        "mma.sync.aligned.m16n8k8.row.col.f32.tf32.tf32.f32 "
        "{%0,%1,%2,%3}, {%4,%5,%6,%7}, {%8,%9}, {%0,%1,%2,%3};"
        : "+f"(d[0]), "+f"(d[1]), "+f"(d[2]), "+f"(d[3])
        : "r"(a[0]), "r"(a[1]), "r"(a[2]), "r"(a[3]), "r"(b0), "r"(b1));
}

#define NT256 ((N_NODES + 255) / 256)    // 391
#define S_MMA0 ((2 * 192 * BSTR + 128) * 4)   // 209408
#define S_MMA1 ((2 * 128 * BSTR) * 4)         // 139264

// MODE 0: sage1  A=[h|hn1] K=192, B=[W1s;W1n], out=relu(.+b1)->g_h1
// MODE 1: sage2  A=g_h1 K=128,    B=[W2s|W2n], out raw ->g_z
template <int MODE>
__global__ void __launch_bounds__(256) k_mma_p(const float* __restrict__ Wa,
                                               const float* __restrict__ Wb,
                                               const float* __restrict__ bias) {
    constexpr int KTOT = (MODE == 0) ? 192 : 128;
    extern __shared__ float sm[];
    float* sBh = sm;
    float* sBl = sm + KTOT * BSTR;
    float* sB  = sm + 2 * KTOT * BSTR;

    for (int i = threadIdx.x; i < KTOT * 128; i += 256) {
        int k = i >> 7, n = i & 127;
        float w;
        if (MODE == 0) w = (k < 96) ? Wa[k * 128 + n] : Wb[(k - 96) * 128 + n];
        else           w = (n < 64) ? Wa[k * 64 + n]  : Wb[k * 64 + (n - 64)];
        float hi, lo; split2(w, hi, lo);
        sBh[k * BSTR + n] = hi;
        sBl[k * BSTR + n] = lo;
    }
    if (MODE == 0)
        for (int i = threadIdx.x; i < 128; i += 256) sB[i] = bias[i];
    __syncthreads();

    int warp = threadIdx.x >> 5, lane = threadIdx.x & 31;
    int gid = lane >> 2, qid = lane & 3;

    for (int tile = blockIdx.x; tile < NT256; tile += gridDim.x) {
        int wbase = tile * 256 + warp * 32;
        if (wbase >= N_NODES) continue;
        bool full = (wbase + 31) < N_NODES;

        float d[2][16][4];
        #pragma unroll
        for (int mt = 0; mt < 2; mt++)
            #pragma unroll
            for (int nb = 0; nb < 16; nb++) {
                d[mt][nb][0]=0.f; d[mt][nb][1]=0.f; d[mt][nb][2]=0.f; d[mt][nb][3]=0.f;
            }

        #pragma unroll 1
        for (int ks = 0; ks < KTOT / 8; ks++) {
            int k0 = ks * 8;
            const float* base;
            int rs;
            if (MODE == 0) {
                base = (k0 < 96) ? (g_h + k0) : (g_hn1 + (k0 - 96));
                rs = CAT_F;
            } else {
                base = g_h1 + k0;
                rs = HID_F;
            }

            uint32_t ah[2][4], al[2][4];
            #pragma unroll
            for (int mt = 0; mt < 2; mt++) {
                int r0 = wbase + mt * 16 + gid;
                int r1 = r0 + 8;
                float f0, f1, f2, f3;
                if (full) {
                    f0 = base[(size_t)r0 * rs + qid];
                    f1 = base[(size_t)r1 * rs + qid];
                    f2 = base[(size_t)r0 * rs + qid + 4];
                    f3 = base[(size_t)r1 * rs + qid + 4];
                } else {
                    f0 = (r0 < N_NODES) ? base[(size_t)r0 * rs + qid]     : 0.f;
                    f1 = (r1 < N_NODES) ? base[(size_t)r1 * rs + qid]     : 0.f;
                    f2 = (r0 < N_NODES) ? base[(size_t)r0 * rs + qid + 4] : 0.f;
                    f3 = (r1 < N_NODES) ? base[(size_t)r1 * rs + qid + 4] : 0.f;
                }
                float h, l;
                split2(f0, h, l); ah[mt][0] = __float_as_uint(h); al[mt][0] = __float_as_uint(l);
                split2(f1, h, l); ah[mt][1] = __float_as_uint(h); al[mt][1] = __float_as_uint(l);
                split2(f2, h, l); ah[mt][2] = __float_as_uint(h); al[mt][2] = __float_as_uint(l);
                split2(f3, h, l); ah[mt][3] = __float_as_uint(h); al[mt][3] = __float_as_uint(l);
            }

            const float* pBh = sBh + (k0 + qid) * BSTR + gid;
            const float* pBl = sBl + (k0 + qid) * BSTR + gid;
            #pragma unroll
            for (int nb = 0; nb < 16; nb++) {
                uint32_t bh0 = __float_as_uint(pBh[nb * 8]);
                uint32_t bh1 = __float_as_uint(pBh[nb * 8 + 4 * BSTR]);
                uint32_t bl0 = __float_as_uint(pBl[nb * 8]);
                uint32_t bl1 = __float_as_uint(pBl[nb * 8 + 4 * BSTR]);
                mma8(d[0][nb], ah[0], bh0, bh1);
                mma8(d[0][nb], al[0], bh0, bh1);
                mma8(d[0][nb], ah[0], bl0, bl1);
                mma8(d[1][nb], ah[1], bh0, bh1);
                mma8(d[1][nb], al[1], bh0, bh1);
                mma8(d[1][nb], ah[1], bl0, bl1);
            }
        }

        #pragma unroll
        for (int mt = 0; mt < 2; mt++) {
            int r0 = wbase + mt * 16 + gid;
            int r1 = r0 + 8;
            #pragma unroll
            for (int nb = 0; nb < 16; nb++) {
                int col = nb * 8 + qid * 2;
                if (MODE == 0) {
                    float b0 = sB[col], b1v = sB[col + 1];
                    if (r0 < N_NODES) {
                        float2 o;
                        o.x = fmaxf(d[mt][nb][0] + b0, 0.f);
                        o.y = fmaxf(d[mt][nb][1] + b1v, 0.f);
                        *(float2*)(g_h1 + (size_t)r0 * HID_F + col) = o;
                    }
                    if (r1 < N_NODES) {
                        float2 o;
                        o.x = fmaxf(d[mt][nb][2] + b0, 0.f);
                        o.y = fmaxf(d[mt][nb][3] + b1v, 0.f);
                        *(float2*)(g_h1 + (size_t)r1 * HID_F + col) = o;
                    }
                } else {
                    if (r0 < N_NODES) {
                        float2 o; o.x = d[mt][nb][0]; o.y = d[mt][nb][1];
                        *(float2*)(g_z + (size_t)r0 * 128 + col) = o;
                    }
                    if (r1 < N_NODES) {
                        float2 o; o.x = d[mt][nb][2]; o.y = d[mt][nb][3];
                        *(float2*)(g_z + (size_t)r1 * 128 + col) = o;
                    }
                }
            }
        }
    }
}

// ---------------- sage2 gather epilogue: out = zs + mean(zn[src]) + b2 ----------------
__global__ void __launch_bounds__(256) k_sage2_gather(const float* __restrict__ b2,
                                                      float* __restrict__ out) {
    int node = (blockIdx.x * 256 + threadIdx.x) >> 5;
    int lane = threadIdx.x & 31;
    if (node >= N_NODES) return;
    int c = lane * 2;

    float2 zs = *(const float2*)(g_z + (size_t)node * 128 + c);

    int lo = g_rowptr[node], hi = g_rowptr[node + 1];
    float2 a0 = make_float2(0.f, 0.f), a1 = make_float2(0.f, 0.f);
    int p = lo;
    for (; p + 1 < hi; p += 2) {
        int s0 = g_csr_src[p], s1 = g_csr_src[p + 1];
        float2 v0 = *(const float2*)(g_z + (size_t)s0 * 128 + 64 + c);
        float2 v1 = *(const float2*)(g_z + (size_t)s1 * 128 + 64 + c);
        a0.x += v0.x; a0.y += v0.y;
        a1.x += v1.x; a1.y += v1.y;
    }
    if (p < hi) {
        int s = g_csr_src[p];
        float2 v = *(const float2*)(g_z + (size_t)s * 128 + 64 + c);
        a0.x += v.x; a0.y += v.y;
    }
    float invd = 1.0f / fmaxf((float)(hi - lo), 1.0f);
    float2 b = *(const float2*)(b2 + c);
    float2 r;
    r.x = zs.x + (a0.x + a1.x) * invd + b.x;
    r.y = zs.y + (a0.y + a1.y) * invd + b.y;
    *(float2*)(out + (size_t)node * OUT_F + c) = r;
}

extern "C" void kernel_launch(void* const* d_in, const int* in_sizes, int n_in,
                              void* d_out, int out_size) {
    const float* nfeat = (const float*)d_in[0];
    const float* efeat = (const float*)d_in[1];
    const int*   src   = (const int*)  d_in[2];
    const int*   dst   = (const int*)  d_in[3];
    const float* We    = (const float*)d_in[4];
    const float* be    = (const float*)d_in[5];
    const float* W1s   = (const float*)d_in[6];
    const float* W1n   = (const float*)d_in[7];
    const float* b1    = (const float*)d_in[8];
    const float* W2s   = (const float*)d_in[9];
    const float* W2n   = (const float*)d_in[10];
    const float* b2    = (const float*)d_in[11];
    float* out = (float*)d_out;

    const int TPB = 256;
    const int edge_blocks = (N_EDGES + TPB - 1) / TPB;
    const int node_blocks = (N_NODES + TPB - 1) / TPB;
    const int g0_blocks   = (N_NODES + 15) / 16;
    const int gw_blocks   = (N_NODES + 7) / 8;

    cudaFuncSetAttribute(k_mma_p<0>, cudaFuncAttributeMaxDynamicSharedMemorySize, S_MMA0);
    cudaFuncSetAttribute(k_mma_p<1>, cudaFuncAttributeMaxDynamicSharedMemorySize, S_MMA1);

    k_zero_hist<<<node_blocks, TPB>>>();
    k_hist     <<<edge_blocks, TPB>>>(dst);
    k_scan     <<<1, SCAN_T>>>();
    k_place    <<<edge_blocks, TPB>>>(src, dst);
    k_edge_mlp <<<edge_blocks, TPB>>>(efeat, nfeat, We, be);
    k_gather0  <<<g0_blocks, TPB>>>(nfeat);
    k_gather_h <<<gw_blocks, TPB>>>();
    k_mma_p<0> <<<148, TPB, S_MMA0>>>(W1s, W1n, b1);
    k_mma_p<1> <<<148, TPB, S_MMA1>>>(W2s, W2n, nullptr);
    k_sage2_gather<<<gw_blocks, TPB>>>(b2, out);
}

// round 14
// speedup vs baseline: 1.2687x; 1.0656x over previous
#include <cuda_runtime.h>
#include <cstddef>
#include <cstdint>

#define N_NODES 100000
#define N_EDGES 1600000
#define IN_F    48
#define EDGE_F  32
#define CAT_F   96
#define HID_F   128
#define OUT_F   64

#define SCAN_T  1024
#define CHUNK   ((N_NODES + SCAN_T - 1) / SCAN_T)

__device__ int   g_deg_i [N_NODES];
__device__ int   g_rowptr[N_NODES + 1];
__device__ int   g_cursor[N_NODES];
__device__ int   g_csr_eid[N_EDGES];
__device__ int   g_csr_src[N_EDGES];
__device__ int   g_csr_dst[N_EDGES];
__device__ float g_sum0[(size_t)N_NODES * IN_F];
__device__ float g_h   [(size_t)N_NODES * CAT_F];
__device__ float g_hn1 [(size_t)N_NODES * CAT_F];
__device__ float g_h1  [(size_t)N_NODES * HID_F];
__device__ float g_z   [(size_t)N_NODES * 128];   // [self(64) | neigh(64)] pre-agg

__device__ __forceinline__ void red_add_v4(float* p, float4 v) {
    asm volatile("red.global.add.v4.f32 [%0], {%1, %2, %3, %4};"
                 :: "l"(p), "f"(v.x), "f"(v.y), "f"(v.z), "f"(v.w) : "memory");
}

// ---------------- zero: deg histogram + sum0 ----------------
__global__ void k_zero2() {
    size_t i = (size_t)blockIdx.x * blockDim.x + threadIdx.x;
    if (i < N_NODES) g_deg_i[i] = 0;
    size_t n4 = (size_t)N_NODES * IN_F / 4;
    if (i < n4) ((float4*)g_sum0)[i] = make_float4(0.f, 0.f, 0.f, 0.f);
}

__global__ void __launch_bounds__(256) k_hist(const int* __restrict__ dst) {
    int e = blockIdx.x * blockDim.x + threadIdx.x;
    if (e < N_EDGES) atomicAdd(&g_deg_i[dst[e]], 1);
}

__global__ void __launch_bounds__(SCAN_T) k_scan() {
    __shared__ int sh[SCAN_T];
    int t = threadIdx.x;
    int start = t * CHUNK;
    int end = start + CHUNK; if (end > N_NODES) end = N_NODES;
    int s = 0;
    if (start < N_NODES) for (int i = start; i < end; i++) s += g_deg_i[i];
    sh[t] = s;
    __syncthreads();
    for (int d = 1; d < SCAN_T; d <<= 1) {
        int v = (t >= d) ? sh[t - d] : 0;
        __syncthreads();
        sh[t] += v;
        __syncthreads();
    }
    int off = sh[t] - s;
    if (start < N_NODES) {
        for (int i = start; i < end; i++) {
            g_rowptr[i] = off;
            g_cursor[i] = off;
            off += g_deg_i[i];
        }
        if (end == N_NODES) g_rowptr[N_NODES] = off;
    }
}

__global__ void __launch_bounds__(256) k_place(const int* __restrict__ src,
                                               const int* __restrict__ dst) {
    int e = blockIdx.x * blockDim.x + threadIdx.x;
    if (e >= N_EDGES) return;
    int d = dst[e];
    int p = atomicAdd(&g_cursor[d], 1);
    g_csr_eid[p] = e;
    g_csr_src[p] = src[e];
    g_csr_dst[p] = d;
}

// ---------------- fused edge MLP + per-dst mean-sum (smem staging) ----------------
// block = 256 consecutive CSR slots (N_EDGES divisible by 256).
#define MSTR 52
#define EF_SMEM ((256 * MSTR + EDGE_F * IN_F + IN_F) * 4)   // 59,584 B

__global__ void __launch_bounds__(256) k_edge_fused(const float* __restrict__ efeat,
                                                    const float* __restrict__ nfeat,
                                                    const float* __restrict__ We,
                                                    const float* __restrict__ be) {
    extern __shared__ float sm[];
    float* sMsg = sm;                       // [256][MSTR]
    float* sWe  = sm + 256 * MSTR;          // [32][48]
    float* sbe  = sWe + EDGE_F * IN_F;      // [48]
    for (int i = threadIdx.x; i < EDGE_F * IN_F; i += 256) sWe[i] = We[i];
    for (int i = threadIdx.x; i < IN_F; i += 256) sbe[i] = be[i];
    __syncthreads();

    int blockStart = blockIdx.x * 256;
    int p   = blockStart + threadIdx.x;
    int eid = g_csr_eid[p];
    int s   = g_csr_src[p];

    // ---- phase 1: thread-per-edge MLP into smem ----
    float ef[EDGE_F];
    const float4* ep = (const float4*)(efeat + (size_t)eid * EDGE_F);
    #pragma unroll
    for (int i = 0; i < EDGE_F / 4; i++) {
        float4 v = ep[i];
        ef[4*i+0] = v.x; ef[4*i+1] = v.y; ef[4*i+2] = v.z; ef[4*i+3] = v.w;
    }
    const float4* np = (const float4*)(nfeat + (size_t)s * IN_F);
    float* myrow = sMsg + threadIdx.x * MSTR;

    #pragma unroll 1
    for (int j = 0; j < IN_F / 4; j++) {
        float4 a;
        a.x = sbe[4*j+0]; a.y = sbe[4*j+1]; a.z = sbe[4*j+2]; a.w = sbe[4*j+3];
        #pragma unroll
        for (int k = 0; k < EDGE_F; k++) {
            float4 w = *(const float4*)&sWe[k * IN_F + 4*j];
            a.x = fmaf(ef[k], w.x, a.x);
            a.y = fmaf(ef[k], w.y, a.y);
            a.z = fmaf(ef[k], w.z, a.z);
            a.w = fmaf(ef[k], w.w, a.w);
        }
        a.x = fmaxf(a.x, 0.f); a.y = fmaxf(a.y, 0.f);
        a.z = fmaxf(a.z, 0.f); a.w = fmaxf(a.w, 0.f);
        float4 nf = np[j];
        a.x *= nf.x; a.y *= nf.y; a.z *= nf.z; a.w *= nf.w;
        *(float4*)(myrow + 4*j) = a;
    }
    __syncthreads();

    // ---- phase 2: half-warp per node, segment-sum from smem ----
    int hw  = threadIdx.x >> 4;     // 0..15
    int sub = threadIdx.x & 15;
    int node0 = g_csr_dst[blockStart];
    int node1 = g_csr_dst[blockStart + 255];

    for (int n = node0 + hw; n <= node1; n += 16) {
        int lo = g_rowptr[n], hi = g_rowptr[n + 1];
        int clo = lo > blockStart ? lo : blockStart;
        int chi = hi < blockStart + 256 ? hi : blockStart + 256;
        if (clo >= chi) continue;
        if (sub < IN_F / 4) {
            float4 acc = make_float4(0.f, 0.f, 0.f, 0.f);
            for (int q = clo; q < chi; q++) {
                float4 v = *(const float4*)(sMsg + (q - blockStart) * MSTR + sub * 4);
                acc.x += v.x; acc.y += v.y; acc.z += v.z; acc.w += v.w;
            }
            float* dstp = g_sum0 + (size_t)n * IN_F + sub * 4;
            if (lo >= blockStart && hi <= blockStart + 256)
                *(float4*)dstp = acc;            // segment exclusive to this block
            else
                red_add_v4(dstp, acc);           // boundary segment
        }
    }
}

// ---------------- build h = [nfeat | sum0/deg] ----------------
__global__ void __launch_bounds__(256) k_build_h(const float* __restrict__ nfeat) {
    int n = blockIdx.x * blockDim.x + threadIdx.x;
    if (n >= N_NODES) return;
    int deg = g_rowptr[n + 1] - g_rowptr[n];
    float invd = 1.0f / fmaxf((float)deg, 1.0f);
    float4*       hp = (float4*)(g_h + (size_t)n * CAT_F);
    const float4* np = (const float4*)(nfeat + (size_t)n * IN_F);
    const float4* sp = (const float4*)(g_sum0 + (size_t)n * IN_F);
    #pragma unroll
    for (int i = 0; i < IN_F / 4; i++) hp[i] = np[i];
    #pragma unroll
    for (int i = 0; i < IN_F / 4; i++) {
        float4 v = sp[i];
        v.x *= invd; v.y *= invd; v.z *= invd; v.w *= invd;
        hp[IN_F/4 + i] = v;
    }
}

// ---------------- gather1: hn1 = mean(h[src]) ----------------
__global__ void __launch_bounds__(256) k_gather_h() {
    int node = (blockIdx.x * 256 + threadIdx.x) >> 5;
    int lane = threadIdx.x & 31;
    if (node >= N_NODES) return;
    bool active = lane < (CAT_F / 4);

    int lo = g_rowptr[node], hi = g_rowptr[node + 1];
    float4 a0 = make_float4(0.f,0.f,0.f,0.f), a1 = make_float4(0.f,0.f,0.f,0.f);
    int p = lo;
    for (; p + 1 < hi; p += 2) {
        int s0 = g_csr_src[p], s1 = g_csr_src[p + 1];
        if (active) {
            float4 v0 = *(const float4*)(g_h + (size_t)s0 * CAT_F + lane * 4);
            float4 v1 = *(const float4*)(g_h + (size_t)s1 * CAT_F + lane * 4);
            a0.x += v0.x; a0.y += v0.y; a0.z += v0.z; a0.w += v0.w;
            a1.x += v1.x; a1.y += v1.y; a1.z += v1.z; a1.w += v1.w;
        }
    }
    if (p < hi) {
        int s = g_csr_src[p];
        if (active) {
            float4 v = *(const float4*)(g_h + (size_t)s * CAT_F + lane * 4);
            a0.x += v.x; a0.y += v.y; a0.z += v.z; a0.w += v.w;
        }
    }
    if (active) {
        float invd = 1.0f / fmaxf((float)(hi - lo), 1.0f);
        float4 acc;
        acc.x = (a0.x + a1.x) * invd; acc.y = (a0.y + a1.y) * invd;
        acc.z = (a0.z + a1.z) * invd; acc.w = (a0.w + a1.w) * invd;
        *(float4*)(g_hn1 + (size_t)node * CAT_F + lane * 4) = acc;
    }
}

// ================= persistent tf32 3x-split mma GEMMs =================
#define BSTR 136

static __device__ __forceinline__ uint32_t f2tf32(float x) {
    uint32_t r;
    asm("cvt.rna.tf32.f32 %0, %1;" : "=r"(r) : "f"(x));
    return r;
}
static __device__ __forceinline__ void split2(float x, float& hi, float& lo) {
    hi = __uint_as_float(f2tf32(x));
    lo = __uint_as_float(f2tf32(x - hi));
}
static __device__ __forceinline__ void mma8(float* d, const uint32_t* a, uint32_t b0, uint32_t b1) {
    asm volatile(
        "mma.sync.aligned.m16n8k8.row.col.f32.tf32.tf32.f32 "
        "{%0,%1,%2,%3}, {%4,%5,%6,%7}, {%8,%9}, {%0,%1,%2,%3};"
        : "+f"(d[0]), "+f"(d[1]), "+f"(d[2]), "+f"(d[3])
        : "r"(a[0]), "r"(a[1]), "r"(a[2]), "r"(a[3]), "r"(b0), "r"(b1));
}

#define NT256 ((N_NODES + 255) / 256)    // 391
#define S_MMA0 ((2 * 192 * BSTR + 128) * 4)   // 209408
#define S_MMA1 ((2 * 128 * BSTR) * 4)         // 139264

// MODE 0: sage1  A=[h|hn1] K=192, B=[W1s;W1n], out=relu(.+b1)->g_h1
// MODE 1: sage2  A=g_h1 K=128,    B=[W2s|W2n], out raw ->g_z
template <int MODE>
__global__ void __launch_bounds__(256) k_mma_p(const float* __restrict__ Wa,
                                               const float* __restrict__ Wb,
                                               const float* __restrict__ bias) {
    constexpr int KTOT = (MODE == 0) ? 192 : 128;
    extern __shared__ float sm[];
    float* sBh = sm;
    float* sBl = sm + KTOT * BSTR;
    float* sB  = sm + 2 * KTOT * BSTR;

    for (int i = threadIdx.x; i < KTOT * 128; i += 256) {
        int k = i >> 7, n = i & 127;
        float w;
        if (MODE == 0) w = (k < 96) ? Wa[k * 128 + n] : Wb[(k - 96) * 128 + n];
        else           w = (n < 64) ? Wa[k * 64 + n]  : Wb[k * 64 + (n - 64)];
        float hi, lo; split2(w, hi, lo);
        sBh[k * BSTR + n] = hi;
        sBl[k * BSTR + n] = lo;
    }
    if (MODE == 0)
        for (int i = threadIdx.x; i < 128; i += 256) sB[i] = bias[i];
    __syncthreads();

    int warp = threadIdx.x >> 5, lane = threadIdx.x & 31;
    int gid = lane >> 2, qid = lane & 3;

    for (int tile = blockIdx.x; tile < NT256; tile += gridDim.x) {
        int wbase = tile * 256 + warp * 32;
        if (wbase >= N_NODES) continue;
        bool full = (wbase + 31) < N_NODES;

        float d[2][16][4];
        #pragma unroll
        for (int mt = 0; mt < 2; mt++)
            #pragma unroll
            for (int nb = 0; nb < 16; nb++) {
                d[mt][nb][0]=0.f; d[mt][nb][1]=0.f; d[mt][nb][2]=0.f; d[mt][nb][3]=0.f;
            }

        #pragma unroll 1
        for (int ks = 0; ks < KTOT / 8; ks++) {
            int k0 = ks * 8;
            const float* base;
            int rs;
            if (MODE == 0) {
                base = (k0 < 96) ? (g_h + k0) : (g_hn1 + (k0 - 96));
                rs = CAT_F;
            } else {
                base = g_h1 + k0;
                rs = HID_F;
            }

            uint32_t ah[2][4], al[2][4];
            #pragma unroll
            for (int mt = 0; mt < 2; mt++) {
                int r0 = wbase + mt * 16 + gid;
                int r1 = r0 + 8;
                float f0, f1, f2, f3;
                if (full) {
                    f0 = base[(size_t)r0 * rs + qid];
                    f1 = base[(size_t)r1 * rs + qid];
                    f2 = base[(size_t)r0 * rs + qid + 4];
                    f3 = base[(size_t)r1 * rs + qid + 4];
                } else {
                    f0 = (r0 < N_NODES) ? base[(size_t)r0 * rs + qid]     : 0.f;
                    f1 = (r1 < N_NODES) ? base[(size_t)r1 * rs + qid]     : 0.f;
                    f2 = (r0 < N_NODES) ? base[(size_t)r0 * rs + qid + 4] : 0.f;
                    f3 = (r1 < N_NODES) ? base[(size_t)r1 * rs + qid + 4] : 0.f;
                }
                float h, l;
                split2(f0, h, l); ah[mt][0] = __float_as_uint(h); al[mt][0] = __float_as_uint(l);
                split2(f1, h, l); ah[mt][1] = __float_as_uint(h); al[mt][1] = __float_as_uint(l);
                split2(f2, h, l); ah[mt][2] = __float_as_uint(h); al[mt][2] = __float_as_uint(l);
                split2(f3, h, l); ah[mt][3] = __float_as_uint(h); al[mt][3] = __float_as_uint(l);
            }

            const float* pBh = sBh + (k0 + qid) * BSTR + gid;
            const float* pBl = sBl + (k0 + qid) * BSTR + gid;
            #pragma unroll
            for (int nb = 0; nb < 16; nb++) {
                uint32_t bh0 = __float_as_uint(pBh[nb * 8]);
                uint32_t bh1 = __float_as_uint(pBh[nb * 8 + 4 * BSTR]);
                uint32_t bl0 = __float_as_uint(pBl[nb * 8]);
                uint32_t bl1 = __float_as_uint(pBl[nb * 8 + 4 * BSTR]);
                mma8(d[0][nb], ah[0], bh0, bh1);
                mma8(d[0][nb], al[0], bh0, bh1);
                mma8(d[0][nb], ah[0], bl0, bl1);
                mma8(d[1][nb], ah[1], bh0, bh1);
                mma8(d[1][nb], al[1], bh0, bh1);
                mma8(d[1][nb], ah[1], bl0, bl1);
            }
        }

        #pragma unroll
        for (int mt = 0; mt < 2; mt++) {
            int r0 = wbase + mt * 16 + gid;
            int r1 = r0 + 8;
            #pragma unroll
            for (int nb = 0; nb < 16; nb++) {
                int col = nb * 8 + qid * 2;
                if (MODE == 0) {
                    float b0 = sB[col], b1v = sB[col + 1];
                    if (r0 < N_NODES) {
                        float2 o;
                        o.x = fmaxf(d[mt][nb][0] + b0, 0.f);
                        o.y = fmaxf(d[mt][nb][1] + b1v, 0.f);
                        *(float2*)(g_h1 + (size_t)r0 * HID_F + col) = o;
                    }
                    if (r1 < N_NODES) {
                        float2 o;
                        o.x = fmaxf(d[mt][nb][2] + b0, 0.f);
                        o.y = fmaxf(d[mt][nb][3] + b1v, 0.f);
                        *(float2*)(g_h1 + (size_t)r1 * HID_F + col) = o;
                    }
                } else {
                    if (r0 < N_NODES) {
                        float2 o; o.x = d[mt][nb][0]; o.y = d[mt][nb][1];
                        *(float2*)(g_z + (size_t)r0 * 128 + col) = o;
                    }
                    if (r1 < N_NODES) {
                        float2 o; o.x = d[mt][nb][2]; o.y = d[mt][nb][3];
                        *(float2*)(g_z + (size_t)r1 * 128 + col) = o;
                    }
                }
            }
        }
    }
}

// ---------------- sage2 gather epilogue: out = zs + mean(zn[src]) + b2 ----------------
__global__ void __launch_bounds__(256) k_sage2_gather(const float* __restrict__ b2,
                                                      float* __restrict__ out) {
    int node = (blockIdx.x * 256 + threadIdx.x) >> 5;
    int lane = threadIdx.x & 31;
    if (node >= N_NODES) return;
    int c = lane * 2;

    float2 zs = *(const float2*)(g_z + (size_t)node * 128 + c);

    int lo = g_rowptr[node], hi = g_rowptr[node + 1];
    float2 a0 = make_float2(0.f, 0.f), a1 = make_float2(0.f, 0.f);
    int p = lo;
    for (; p + 1 < hi; p += 2) {
        int s0 = g_csr_src[p], s1 = g_csr_src[p + 1];
        float2 v0 = *(const float2*)(g_z + (size_t)s0 * 128 + 64 + c);
        float2 v1 = *(const float2*)(g_z + (size_t)s1 * 128 + 64 + c);
        a0.x += v0.x; a0.y += v0.y;
        a1.x += v1.x; a1.y += v1.y;
    }
    if (p < hi) {
        int s = g_csr_src[p];
        float2 v = *(const float2*)(g_z + (size_t)s * 128 + 64 + c);
        a0.x += v.x; a0.y += v.y;
    }
    float invd = 1.0f / fmaxf((float)(hi - lo), 1.0f);
    float2 b = *(const float2*)(b2 + c);
    float2 r;
    r.x = zs.x + (a0.x + a1.x) * invd + b.x;
    r.y = zs.y + (a0.y + a1.y) * invd + b.y;
    *(float2*)(out + (size_t)node * OUT_F + c) = r;
}

extern "C" void kernel_launch(void* const* d_in, const int* in_sizes, int n_in,
                              void* d_out, int out_size) {
    const float* nfeat = (const float*)d_in[0];
    const float* efeat = (const float*)d_in[1];
    const int*   src   = (const int*)  d_in[2];
    const int*   dst   = (const int*)  d_in[3];
    const float* We    = (const float*)d_in[4];
    const float* be    = (const float*)d_in[5];
    const float* W1s   = (const float*)d_in[6];
    const float* W1n   = (const float*)d_in[7];
    const float* b1    = (const float*)d_in[8];
    const float* W2s   = (const float*)d_in[9];
    const float* W2n   = (const float*)d_in[10];
    const float* b2    = (const float*)d_in[11];
    float* out = (float*)d_out;

    const int TPB = 256;
    const int edge_blocks = N_EDGES / TPB;            // 6250, exact
    const int node_blocks = (N_NODES + TPB - 1) / TPB;
    const int zero_blocks = ((N_NODES * IN_F / 4) + TPB - 1) / TPB;
    const int gw_blocks   = (N_NODES + 7) / 8;

    cudaFuncSetAttribute(k_edge_fused, cudaFuncAttributeMaxDynamicSharedMemorySize, EF_SMEM);
    cudaFuncSetAttribute(k_mma_p<0>, cudaFuncAttributeMaxDynamicSharedMemorySize, S_MMA0);
    cudaFuncSetAttribute(k_mma_p<1>, cudaFuncAttributeMaxDynamicSharedMemorySize, S_MMA1);

    k_zero2     <<<zero_blocks, TPB>>>();
    k_hist      <<<edge_blocks, TPB>>>(dst);
    k_scan      <<<1, SCAN_T>>>();
    k_place     <<<edge_blocks, TPB>>>(src, dst);
    k_edge_fused<<<edge_blocks, TPB, EF_SMEM>>>(efeat, nfeat, We, be);
    k_build_h   <<<node_blocks, TPB>>>(nfeat);
    k_gather_h  <<<gw_blocks, TPB>>>();
    k_mma_p<0>  <<<148, TPB, S_MMA0>>>(W1s, W1n, b1);
    k_mma_p<1>  <<<148, TPB, S_MMA1>>>(W2s, W2n, nullptr);
    k_sage2_gather<<<gw_blocks, TPB>>>(b2, out);
}